// round 4
// baseline (speedup 1.0000x reference)
#include <cuda_runtime.h>
#include <math.h>

#define N_ANCH 21840
#define NWORDS 342            // ceil(21840/64) mask row width (u64 words)
#define HPAIR  171            // NWORDS/2 (ulonglong2 per row)
#define NBLK   86             // ceil(21840/256)
#define NDIG   4096           // 12-bit radix
#define NMS_THF 0.3f
#define FIN_THF 0.5f
#define FULLM 0xFFFFFFFFu
#define KINV  0x00FFFFFFu     // invalid (score<=0.5) sort key: larger than any valid key

// ---- static device scratch ----
__device__ float g_x1[N_ANCH], g_y1[N_ANCH], g_x2[N_ANCH], g_y2[N_ANCH];
__device__ float g_sc[N_ANCH], g_area[N_ANCH];
__device__ unsigned g_keyA[N_ANCH], g_keyB[N_ANCH];
__device__ unsigned short g_valA[N_ANCH], g_valB[N_ANCH];
__device__ int g_hist[NBLK * NDIG], g_off[NBLK * NDIG];
__device__ int g_srank[N_ANCH];
__device__ int g_kcnt;
__device__ float g_tminx1[NWORDS], g_tminy1[NWORDS], g_tmaxx2[NWORDS], g_tmaxy2[NWORDS];
__device__ float g_tamin[NWORDS], g_tamax[NWORDS];
__device__ unsigned long long g_mask[(size_t)N_ANCH * NWORDS];  // rank-space forward bitmask
__device__ unsigned long long g_keepw[NWORDS];

struct InPtrs { const float* cls[6]; const float* reg[6]; };

// ---------------- K1: decode (bit-exact vs reference) ----------------
__global__ void k_decode(InPtrs in) {
    int i = blockIdx.x * blockDim.x + threadIdx.x;
    if (i >= N_ANCH) return;
    const int offs[7]   = {0, 16384, 20480, 21504, 21760, 21824, 21840};
    const int maps[6]   = {128, 64, 32, 16, 8, 4};
    const float strd[6] = {4.f, 8.f, 16.f, 32.f, 64.f, 128.f};
    int sc = 0;
    #pragma unroll
    for (int k = 0; k < 5; k++) if (i >= offs[k + 1]) sc = k + 1;
    int local = i - offs[sc];
    int W = maps[sc];
    int y = local / W, x = local - y * W;
    int HW = W * W;
    const float* cls = in.cls[sc];
    const float* reg = in.reg[sc];

    float c0 = cls[local], c1 = cls[HW + local];
    float m  = fmaxf(c0, c1);
    float e0 = expf(__fsub_rn(c0, m));
    float e1 = expf(__fsub_rn(c1, m));
    float prob = __fdiv_rn(e1, __fadd_rn(e0, e1));

    float s   = strd[sc];
    float pwh = s * 4.0f;
    float pcx = __fadd_rn(0.5f * s, __fmul_rn((float)x, s));
    float pcy = __fadd_rn(0.5f * s, __fmul_rn((float)y, s));
    float l0 = reg[local], l1 = reg[HW + local];
    float l2 = reg[2 * HW + local], l3 = reg[3 * HW + local];
    float cx = __fadd_rn(pcx, __fmul_rn(__fmul_rn(l0, 0.1f), pwh));
    float cy = __fadd_rn(pcy, __fmul_rn(__fmul_rn(l1, 0.1f), pwh));
    float w  = __fmul_rn(pwh, expf(__fmul_rn(l2, 0.2f)));
    float h  = __fmul_rn(pwh, expf(__fmul_rn(l3, 0.2f)));
    float x1 = __fsub_rn(cx, __fmul_rn(w, 0.5f));
    float y1 = __fsub_rn(cy, __fmul_rn(h, 0.5f));
    float x2 = __fadd_rn(x1, w);
    float y2 = __fadd_rn(y1, h);

    g_x1[i] = x1; g_y1[i] = y1; g_x2[i] = x2; g_y2[i] = y2; g_sc[i] = prob;
    g_area[i] = __fmul_rn(__fadd_rn(__fsub_rn(x2, x1), 1.0f),
                          __fadd_rn(__fsub_rn(y2, y1), 1.0f));

    // 24-bit key: prob in (0.5,1] => ~(bits|0x80000000) - 0x407FFFFF in [0,0x7FFFFF].
    // ascending key == descending score, stable sort => ascending index ties.
    unsigned u   = __float_as_uint(prob);
    unsigned k24 = (~(u | 0x80000000u)) - 0x407FFFFFu;
    g_keyA[i] = (prob > FIN_THF) ? k24 : KINV;
    g_valA[i] = (unsigned short)i;
}

// ---------------- tile bounding boxes (only score>0.5 boxes) ----------------
__global__ void k_tilebb() {
    __shared__ float m0[64], m1[64], m2[64], m3[64], m4[64], m5[64];
    int t = threadIdx.x;
    int j = blockIdx.x * 64 + t;
    bool on = (j < N_ANCH) && (g_sc[j] > FIN_THF);
    float a = on ? g_area[j] : 0.f;
    m0[t] = on ? g_x1[j] :  1e30f;
    m1[t] = on ? g_y1[j] :  1e30f;
    m2[t] = on ? g_x2[j] : -1e30f;
    m3[t] = on ? g_y2[j] : -1e30f;
    m4[t] = on ? a :  1e30f;
    m5[t] = on ? a : -1e30f;
    for (int s = 32; s > 0; s >>= 1) {
        __syncthreads();
        if (t < s) {
            m0[t] = fminf(m0[t], m0[t + s]);
            m1[t] = fminf(m1[t], m1[t + s]);
            m2[t] = fmaxf(m2[t], m2[t + s]);
            m3[t] = fmaxf(m3[t], m3[t + s]);
            m4[t] = fminf(m4[t], m4[t + s]);
            m5[t] = fmaxf(m5[t], m5[t + s]);
        }
    }
    if (t == 0) {
        g_tminx1[blockIdx.x] = m0[0]; g_tminy1[blockIdx.x] = m1[0];
        g_tmaxx2[blockIdx.x] = m2[0]; g_tmaxy2[blockIdx.x] = m3[0];
        g_tamin[blockIdx.x]  = m4[0]; g_tamax[blockIdx.x]  = m5[0];
    }
}

// ---------------- radix sort: 2 passes of 12 bits, stable LSD ----------------
__global__ void k_hist(const unsigned* __restrict__ key, int shift) {
    __shared__ int h[NDIG];
    int t = threadIdx.x;
    for (int q = t; q < NDIG; q += 256) h[q] = 0;
    __syncthreads();
    int i = blockIdx.x * 256 + t;
    if (i < N_ANCH) atomicAdd(&h[(key[i] >> shift) & 4095u], 1);
    __syncthreads();
    for (int q = t; q < NDIG; q += 256) g_hist[blockIdx.x * NDIG + q] = h[q];
}

__global__ void __launch_bounds__(1024) k_scanhist() {
    __shared__ int wsum[32];
    int t = threadIdx.x;
    int run[4] = {0, 0, 0, 0};
    for (int bb = 0; bb < NBLK; bb += 8) {
        int v[8][4];
        #pragma unroll
        for (int k = 0; k < 8; k++) {
            int b = bb + k;
            #pragma unroll
            for (int q = 0; q < 4; q++)
                v[k][q] = (b < NBLK) ? g_hist[b * NDIG + t * 4 + q] : 0;
        }
        #pragma unroll
        for (int k = 0; k < 8; k++) {
            int b = bb + k;
            if (b < NBLK) {
                #pragma unroll
                for (int q = 0; q < 4; q++) {
                    g_off[b * NDIG + t * 4 + q] = run[q];
                    run[q] += v[k][q];
                }
            }
        }
    }
    int tot = run[0] + run[1] + run[2] + run[3];
    int lane = t & 31, wid = t >> 5;
    int x = tot;
    #pragma unroll
    for (int s = 1; s < 32; s <<= 1) {
        int y = __shfl_up_sync(FULLM, x, s);
        if (lane >= s) x += y;
    }
    if (lane == 31) wsum[wid] = x;
    __syncthreads();
    if (wid == 0) {
        int wv = wsum[lane];
        #pragma unroll
        for (int s = 1; s < 32; s <<= 1) {
            int y = __shfl_up_sync(FULLM, wv, s);
            if (lane >= s) wv += y;
        }
        wsum[lane] = wv;
    }
    __syncthreads();
    int base = x - tot + ((wid > 0) ? wsum[wid - 1] : 0);
    int d0 = base, d1 = d0 + run[0], d2 = d1 + run[1], d3 = d2 + run[2];
    int dbase[4] = {d0, d1, d2, d3};
    for (int bb = 0; bb < NBLK; bb += 8) {
        #pragma unroll
        for (int k = 0; k < 8; k++) {
            int b = bb + k;
            if (b < NBLK) {
                #pragma unroll
                for (int q = 0; q < 4; q++)
                    g_off[b * NDIG + t * 4 + q] += dbase[q];
            }
        }
    }
}

__global__ void k_scatter(const unsigned* __restrict__ keyin,
                          const unsigned short* __restrict__ valin,
                          unsigned* __restrict__ keyout,
                          unsigned short* __restrict__ valout, int shift) {
    __shared__ int cnt[NDIG];
    __shared__ int boff[NDIG];
    int t = threadIdx.x;
    for (int q = t; q < NDIG; q += 256) {
        cnt[q] = 0;
        boff[q] = g_off[blockIdx.x * NDIG + q];
    }
    __syncthreads();
    int i = blockIdx.x * 256 + t;
    bool on = i < N_ANCH;
    unsigned k = 0; unsigned short v = 0;
    if (on) { k = keyin[i]; v = valin[i]; }
    unsigned d = (k >> shift) & 4095u;
    int lane = t & 31, wid = t >> 5;
    unsigned wactive = __ballot_sync(FULLM, on);
    int lrank = 0;
    for (int w = 0; w < 8; w++) {
        if (wid == w && on) {
            unsigned peers = __match_any_sync(wactive, d);
            int leader = __ffs(peers) - 1;
            int gsz = __popc(peers);
            int old = 0;
            if (lane == leader) old = atomicAdd(&cnt[d], gsz);
            old = __shfl_sync(peers, old, leader);
            lrank = old + __popc(peers & ((1u << lane) - 1));
        }
        __syncthreads();
    }
    if (on) {
        int pos = boff[d] + lrank;
        keyout[pos] = k;
        valout[pos] = v;
    }
}

// ---------------- srank + valid count ----------------
__global__ void k_srank() {
    int r = blockIdx.x * blockDim.x + threadIdx.x;
    if (r >= N_ANCH) return;
    unsigned k = g_keyA[r];
    g_srank[g_valA[r]] = r;
    bool inv  = (k == KINV);
    bool pinv = (r == 0) ? false : (g_keyA[r - 1] == KINV);
    if (inv && !pinv) g_kcnt = r;
    if (r == N_ANCH - 1 && !inv) g_kcnt = N_ANCH;
}

// ---------------- zero live region of mask ----------------
__global__ void k_zero() {
    int r = blockIdx.x;
    int kcnt = g_kcnt;
    if (r >= kcnt) return;
    int kw = (kcnt + 63) >> 6;
    int np = (kw + 2) >> 1;   // u2 pairs, covers all read/written words
    ulonglong2* row = (ulonglong2*)(g_mask + (size_t)r * NWORDS);
    ulonglong2 z = make_ulonglong2(0ull, 0ull);
    for (int p = threadIdx.x; p < np; p += 64) row[p] = z;
}

// ---------------- sparse suppression bits (warp per box) ----------------
__global__ void k_nbr() {
    int i = (blockIdx.x * blockDim.x + threadIdx.x) >> 5;
    int lane = threadIdx.x & 31;
    if (i >= N_ANCH) return;
    if (!(g_sc[i] > FIN_THF)) return;
    float x1 = g_x1[i], y1 = g_y1[i], x2 = g_x2[i], y2 = g_y2[i], ai = g_area[i];
    int ri = g_srank[i];
    unsigned long long mybit = 1ull << (ri & 63);
    int myw = ri >> 6;
    for (int tb = 0; tb < NWORDS; tb += 32) {
        int t = tb + lane;
        bool act = false;
        if (t < NWORDS) {
            float bw = __fadd_rn(__fsub_rn(fminf(x2, g_tmaxx2[t]), fmaxf(x1, g_tminx1[t])), 1.0f);
            float bh = __fadd_rn(__fsub_rn(fminf(y2, g_tmaxy2[t]), fmaxf(y1, g_tminy1[t])), 1.0f);
            float lo = fminf(ai, g_tamax[t]);
            float hi = fmaxf(ai, g_tamin[t]);
            act = (bw > 0.f) && (bh > 0.f) && (lo > 0.299f * hi);  // conservative
        }
        unsigned bal = __ballot_sync(FULLM, act);
        while (bal) {
            int tt = __ffs(bal) - 1;
            bal &= bal - 1;
            int j0 = (tb + tt) << 6;
            #pragma unroll
            for (int h = 0; h < 2; h++) {
                int j = j0 + h * 32 + lane;
                if (j < N_ANCH) {
                    int rj = g_srank[j];
                    if (rj < ri) {   // j is a potential suppressor (implies j valid)
                        float xx1 = fmaxf(x1, g_x1[j]);
                        float yy1 = fmaxf(y1, g_y1[j]);
                        float xx2 = fminf(x2, g_x2[j]);
                        float yy2 = fminf(y2, g_y2[j]);
                        float w  = fmaxf(__fadd_rn(__fsub_rn(xx2, xx1), 1.f), 0.f);
                        float hh = fmaxf(__fadd_rn(__fsub_rn(yy2, yy1), 1.f), 0.f);
                        float inter = __fmul_rn(w, hh);
                        float aj = g_area[j];
                        if (inter > 0.299f * fmaxf(ai, aj)) {
                            float iou = __fdiv_rn(inter, __fsub_rn(__fadd_rn(ai, aj), inter));
                            if (iou > NMS_THF)
                                atomicOr(&g_mask[(size_t)rj * NWORDS + myw], mybit);
                        }
                    }
                }
            }
        }
    }
}

// ---------------- word-synchronous greedy scan (1 block) ----------------
__global__ void __launch_bounds__(192) k_scan() {
    __shared__ unsigned long long removed[NWORDS];
    __shared__ unsigned long long dwbuf[2][64];
    __shared__ unsigned long long s_kbits;
    int t = threadIdx.x;
    for (int w = t; w < NWORDS; w += 192) removed[w] = 0;
    int kcnt = g_kcnt;
    int kw = (kcnt + 63) >> 6;
    bool pown = (t < ((kw + 1) >> 1));
    const ulonglong2* mask2 = (const ulonglong2*)g_mask;

    if (t < 64) {   // preload diagonal words of word 0
        int r = t;
        dwbuf[0][t] = (r < kcnt) ? g_mask[(size_t)r * NWORDS + 0] : 0ull;
    }
    __syncthreads();

    for (int w = 0; w < kw; w++) {
        int nb = w & 1;
        // preload diagonal words of word w+1 (threads 64-127)
        if (t >= 64 && t < 128 && (w + 1) < kw) {
            int r = (w + 1) * 64 + (t - 64);
            dwbuf[nb ^ 1][t - 64] = (r < kcnt) ? g_mask[(size_t)r * NWORDS + (w + 1)] : 0ull;
        }
        if (t == 0) {   // serial intra-word greedy chain (register state)
            unsigned long long rw = removed[w];
            unsigned long long kb = 0;
            int lim = min(64, kcnt - w * 64);
            for (int b = 0; b < lim; b++) {
                if (((rw >> b) & 1ull) == 0ull) {
                    kb |= 1ull << b;
                    rw |= dwbuf[nb][b];
                }
            }
            s_kbits = kb;
            g_keepw[w] = kb;
        }
        __syncthreads();
        unsigned long long kb = s_kbits;
        if (pown && kb) {   // batch-OR kept rows into removed
            unsigned long long acc0 = 0, acc1 = 0;
            unsigned long long kk = kb;
            while (kk) {
                int b = __ffsll(kk) - 1;
                kk &= kk - 1;
                ulonglong2 v = mask2[(size_t)(w * 64 + b) * HPAIR + t];
                acc0 |= v.x; acc1 |= v.y;
            }
            removed[2 * t]     |= acc0;
            removed[2 * t + 1] |= acc1;
        }
        __syncthreads();
    }
    for (int ww = kw + t; ww < NWORDS; ww += 192) g_keepw[ww] = 0;
}

// ---------------- final masked write ----------------
__global__ void k_final(float* __restrict__ out) {
    int i = blockIdx.x * blockDim.x + threadIdx.x;
    if (i >= N_ANCH) return;
    float sc = g_sc[i];
    int ri = g_srank[i];
    bool kp = ((g_keepw[ri >> 6] >> (ri & 63)) & 1ull) != 0ull;
    float f = kp ? 1.0f : 0.0f;
    out[i * 5 + 0] = __fmul_rn(g_x1[i], f);
    out[i * 5 + 1] = __fmul_rn(g_y1[i], f);
    out[i * 5 + 2] = __fmul_rn(g_x2[i], f);
    out[i * 5 + 3] = __fmul_rn(g_y2[i], f);
    out[i * 5 + 4] = __fmul_rn(sc, f);
}

extern "C" void kernel_launch(void* const* d_in, const int* in_sizes, int n_in,
                              void* d_out, int out_size) {
    (void)in_sizes; (void)n_in; (void)out_size;
    InPtrs p;
    for (int i = 0; i < 6; i++) {
        p.cls[i] = (const float*)d_in[2 * i];
        p.reg[i] = (const float*)d_in[2 * i + 1];
    }
    unsigned *kA, *kB; unsigned short *vA, *vB;
    cudaGetSymbolAddress((void**)&kA, g_keyA);
    cudaGetSymbolAddress((void**)&kB, g_keyB);
    cudaGetSymbolAddress((void**)&vA, g_valA);
    cudaGetSymbolAddress((void**)&vB, g_valB);

    k_decode<<<NBLK, 256>>>(p);
    k_tilebb<<<NWORDS, 64>>>();

    // 2-pass 12-bit stable LSD radix (A->B->A)
    k_hist<<<NBLK, 256>>>(kA, 0);
    k_scanhist<<<1, 1024>>>();
    k_scatter<<<NBLK, 256>>>(kA, vA, kB, vB, 0);
    k_hist<<<NBLK, 256>>>(kB, 12);
    k_scanhist<<<1, 1024>>>();
    k_scatter<<<NBLK, 256>>>(kB, vB, kA, vA, 12);

    k_srank<<<NBLK, 256>>>();
    k_zero<<<N_ANCH, 64>>>();
    k_nbr<<<(N_ANCH * 32 + 255) / 256, 256>>>();
    k_scan<<<1, 192>>>();
    k_final<<<NBLK, 256>>>((float*)d_out);
}

// round 5
// speedup vs baseline: 7.6992x; 7.6992x over previous
#include <cuda_runtime.h>
#include <math.h>

#define N_ANCH 21840
#define NWORDS 342            // ceil(21840/64)
#define NSTATE 683            // ceil(21840/32), 2 bits per rank
#define NBLK   86             // ceil(21840/256)
#define NDIG   4096           // 12-bit radix
#define CAP    192            // max higher-rank suppressors per box
#define NMS_THF 0.3f
#define FIN_THF 0.5f
#define FULLM 0xFFFFFFFFu
#define KINV  0x00FFFFFFu     // invalid (score<=0.5) key: larger than any valid key

// ---- static device scratch ----
__device__ float g_x1[N_ANCH], g_y1[N_ANCH], g_x2[N_ANCH], g_y2[N_ANCH];
__device__ float g_sc[N_ANCH], g_area[N_ANCH];
__device__ unsigned g_keyA[N_ANCH], g_keyB[N_ANCH];
__device__ unsigned short g_valA[N_ANCH], g_valB[N_ANCH];
__device__ int g_histT[NDIG * NBLK];     // digit-major
__device__ int g_off[NDIG * NBLK];       // digit-major per-block exclusive offsets
__device__ int g_dtot[NDIG], g_dbase[NDIG];
__device__ int g_srank[N_ANCH];
__device__ int g_kcnt;
__device__ float g_tminx1[NWORDS], g_tminy1[NWORDS], g_tmaxx2[NWORDS], g_tmaxy2[NWORDS];
__device__ float g_tamin[NWORDS], g_tamax[NWORDS];
__device__ unsigned short g_nbr[(size_t)N_ANCH * CAP];  // by rank
__device__ int g_ncnt[N_ANCH];                           // by rank
__device__ unsigned long long g_state[NSTATE];

struct InPtrs { const float* cls[6]; const float* reg[6]; };

// ---------------- K1: decode (bit-exact) + fused tile bboxes ----------------
__global__ void k_decode(InPtrs in) {
    __shared__ float m0[256], m1[256], m2[256], m3[256], m4[256], m5[256];
    int t = threadIdx.x;
    int i = blockIdx.x * 256 + t;
    bool on = i < N_ANCH;

    float x1 = 0.f, y1 = 0.f, x2 = 0.f, y2 = 0.f, prob = 0.f, area = 0.f;
    if (on) {
        const int offs[7]   = {0, 16384, 20480, 21504, 21760, 21824, 21840};
        const int maps[6]   = {128, 64, 32, 16, 8, 4};
        const float strd[6] = {4.f, 8.f, 16.f, 32.f, 64.f, 128.f};
        int sc = 0;
        #pragma unroll
        for (int k = 0; k < 5; k++) if (i >= offs[k + 1]) sc = k + 1;
        int local = i - offs[sc];
        int W = maps[sc];
        int y = local / W, x = local - y * W;
        int HW = W * W;
        const float* cls = in.cls[sc];
        const float* reg = in.reg[sc];

        float c0 = cls[local], c1 = cls[HW + local];
        float m  = fmaxf(c0, c1);
        float e0 = expf(__fsub_rn(c0, m));
        float e1 = expf(__fsub_rn(c1, m));
        prob = __fdiv_rn(e1, __fadd_rn(e0, e1));

        float s   = strd[sc];
        float pwh = s * 4.0f;
        float pcx = __fadd_rn(0.5f * s, __fmul_rn((float)x, s));
        float pcy = __fadd_rn(0.5f * s, __fmul_rn((float)y, s));
        float l0 = reg[local], l1 = reg[HW + local];
        float l2 = reg[2 * HW + local], l3 = reg[3 * HW + local];
        float cx = __fadd_rn(pcx, __fmul_rn(__fmul_rn(l0, 0.1f), pwh));
        float cy = __fadd_rn(pcy, __fmul_rn(__fmul_rn(l1, 0.1f), pwh));
        float w  = __fmul_rn(pwh, expf(__fmul_rn(l2, 0.2f)));
        float h  = __fmul_rn(pwh, expf(__fmul_rn(l3, 0.2f)));
        x1 = __fsub_rn(cx, __fmul_rn(w, 0.5f));
        y1 = __fsub_rn(cy, __fmul_rn(h, 0.5f));
        x2 = __fadd_rn(x1, w);
        y2 = __fadd_rn(y1, h);
        area = __fmul_rn(__fadd_rn(__fsub_rn(x2, x1), 1.0f),
                         __fadd_rn(__fsub_rn(y2, y1), 1.0f));

        g_x1[i] = x1; g_y1[i] = y1; g_x2[i] = x2; g_y2[i] = y2;
        g_sc[i] = prob; g_area[i] = area;

        // 24-bit key: prob in (0.5,1] -> [0,0x7FFFFF]; ascending key == descending score
        unsigned u   = __float_as_uint(prob);
        unsigned k24 = (~(u | 0x80000000u)) - 0x407FFFFFu;
        g_keyA[i] = (prob > FIN_THF) ? k24 : KINV;
        g_valA[i] = (unsigned short)i;
    }

    // fused per-64 tile bboxes (over valid boxes only)
    bool v = on && (prob > FIN_THF);
    m0[t] = v ? x1 :  1e30f;
    m1[t] = v ? y1 :  1e30f;
    m2[t] = v ? x2 : -1e30f;
    m3[t] = v ? y2 : -1e30f;
    m4[t] = v ? area :  1e30f;
    m5[t] = v ? area : -1e30f;
    int o = t & 63;
    for (int s = 32; s > 0; s >>= 1) {
        __syncthreads();
        if (o < s) {
            m0[t] = fminf(m0[t], m0[t + s]);
            m1[t] = fminf(m1[t], m1[t + s]);
            m2[t] = fmaxf(m2[t], m2[t + s]);
            m3[t] = fmaxf(m3[t], m3[t + s]);
            m4[t] = fminf(m4[t], m4[t + s]);
            m5[t] = fmaxf(m5[t], m5[t + s]);
        }
    }
    if (o == 0) {
        int tile = blockIdx.x * 4 + (t >> 6);
        if (tile < NWORDS) {
            g_tminx1[tile] = m0[t]; g_tminy1[tile] = m1[t];
            g_tmaxx2[tile] = m2[t]; g_tmaxy2[tile] = m3[t];
            g_tamin[tile]  = m4[t]; g_tamax[tile]  = m5[t];
        }
    }
}

// ---------------- radix sort: 2 passes of 12 bits ----------------
__global__ void k_hist(const unsigned* __restrict__ key, int shift) {
    __shared__ int h[NDIG];
    int t = threadIdx.x;
    for (int q = t; q < NDIG; q += 256) h[q] = 0;
    __syncthreads();
    int i = blockIdx.x * 256 + t;
    if (i < N_ANCH) atomicAdd(&h[(key[i] >> shift) & 4095u], 1);
    __syncthreads();
    for (int q = t; q < NDIG; q += 256) g_histT[q * NBLK + blockIdx.x] = h[q];
}

// warp per digit: scan 86 per-block counts (coalesced digit-major reads)
__global__ void k_scan1() {   // grid 512, block 256
    int w = threadIdx.x >> 5, lane = threadIdx.x & 31;
    int d = blockIdx.x * 8 + w;
    const int* src = g_histT + d * NBLK;
    int v0 = src[lane];
    int v1 = src[lane + 32];
    int v2 = (lane + 64 < NBLK) ? src[lane + 64] : 0;
    int s0 = v0, s1 = v1, s2 = v2;
    #pragma unroll
    for (int s = 1; s < 32; s <<= 1) {
        int a = __shfl_up_sync(FULLM, s0, s); if (lane >= s) s0 += a;
        int b = __shfl_up_sync(FULLM, s1, s); if (lane >= s) s1 += b;
        int c = __shfl_up_sync(FULLM, s2, s); if (lane >= s) s2 += c;
    }
    int t0 = __shfl_sync(FULLM, s0, 31);
    int t1 = __shfl_sync(FULLM, s1, 31);
    int t2 = __shfl_sync(FULLM, s2, 31);
    int* dst = g_off + d * NBLK;
    dst[lane]      = s0 - v0;
    dst[lane + 32] = t0 + s1 - v1;
    if (lane + 64 < NBLK) dst[lane + 64] = t0 + t1 + s2 - v2;
    if (lane == 0) g_dtot[d] = t0 + t1 + t2;
}

__global__ void __launch_bounds__(1024) k_scan2() {   // 1 block: exclusive scan of 4096 totals
    __shared__ int wsum[32];
    int t = threadIdx.x, lane = t & 31, wid = t >> 5;
    int a0 = g_dtot[4 * t], a1 = g_dtot[4 * t + 1], a2 = g_dtot[4 * t + 2], a3 = g_dtot[4 * t + 3];
    int s = a0 + a1 + a2 + a3;
    int x = s;
    #pragma unroll
    for (int k = 1; k < 32; k <<= 1) { int y = __shfl_up_sync(FULLM, x, k); if (lane >= k) x += y; }
    if (lane == 31) wsum[wid] = x;
    __syncthreads();
    if (wid == 0) {
        int wv = wsum[lane];
        #pragma unroll
        for (int k = 1; k < 32; k <<= 1) { int y = __shfl_up_sync(FULLM, wv, k); if (lane >= k) wv += y; }
        wsum[lane] = wv;
    }
    __syncthreads();
    int base = x - s + ((wid > 0) ? wsum[wid - 1] : 0);
    g_dbase[4 * t] = base;
    g_dbase[4 * t + 1] = base + a0;
    g_dbase[4 * t + 2] = base + a0 + a1;
    g_dbase[4 * t + 3] = base + a0 + a1 + a2;
}

__global__ void k_scatter(const unsigned* __restrict__ keyin,
                          const unsigned short* __restrict__ valin,
                          unsigned* __restrict__ keyout,
                          unsigned short* __restrict__ valout, int shift) {
    __shared__ int cnt[NDIG];
    __shared__ int boff[NDIG];
    int t = threadIdx.x;
    for (int q = t; q < NDIG; q += 256) {
        cnt[q] = 0;
        boff[q] = g_off[q * NBLK + blockIdx.x] + g_dbase[q];
    }
    __syncthreads();
    int i = blockIdx.x * 256 + t;
    bool on = i < N_ANCH;
    unsigned k = 0; unsigned short v = 0;
    if (on) { k = keyin[i]; v = valin[i]; }
    unsigned d = (k >> shift) & 4095u;
    int lane = t & 31, wid = t >> 5;
    unsigned wactive = __ballot_sync(FULLM, on);
    int lrank = 0;
    for (int w = 0; w < 8; w++) {
        if (wid == w && on) {
            unsigned peers = __match_any_sync(wactive, d);
            int leader = __ffs(peers) - 1;
            int gsz = __popc(peers);
            int old = 0;
            if (lane == leader) old = atomicAdd(&cnt[d], gsz);
            old = __shfl_sync(peers, old, leader);
            lrank = old + __popc(peers & ((1u << lane) - 1));
        }
        __syncthreads();
    }
    if (on) {
        int pos = boff[d] + lrank;
        keyout[pos] = k;
        valout[pos] = v;
    }
}

// ---------------- srank + valid count ----------------
__global__ void k_srank() {
    int r = blockIdx.x * blockDim.x + threadIdx.x;
    if (r >= N_ANCH) return;
    unsigned k = g_keyA[r];
    g_srank[g_valA[r]] = r;
    bool inv  = (k == KINV);
    bool pinv = (r == 0) ? false : (g_keyA[r - 1] == KINV);
    if (inv && !pinv) g_kcnt = r;
    if (r == N_ANCH - 1 && !inv) g_kcnt = N_ANCH;
}

// ---------------- sparse suppressor lists (warp per box, rank-indexed) ----------------
__global__ void k_nbr() {
    int i = (blockIdx.x * blockDim.x + threadIdx.x) >> 5;
    int lane = threadIdx.x & 31;
    if (i >= N_ANCH) return;
    if (!(g_sc[i] > FIN_THF)) return;
    float x1 = g_x1[i], y1 = g_y1[i], x2 = g_x2[i], y2 = g_y2[i], ai = g_area[i];
    int ri = g_srank[i];
    int cnt = 0;
    for (int tb = 0; tb < NWORDS; tb += 32) {
        int t = tb + lane;
        bool act = false;
        if (t < NWORDS) {
            float bw = __fadd_rn(__fsub_rn(fminf(x2, g_tmaxx2[t]), fmaxf(x1, g_tminx1[t])), 1.0f);
            float bh = __fadd_rn(__fsub_rn(fminf(y2, g_tmaxy2[t]), fmaxf(y1, g_tminy1[t])), 1.0f);
            float lo = fminf(ai, g_tamax[t]);
            float hi = fmaxf(ai, g_tamin[t]);
            act = (bw > 0.f) && (bh > 0.f) && (lo > 0.299f * hi);  // conservative
        }
        unsigned bal = __ballot_sync(FULLM, act);
        while (bal) {
            int tt = __ffs(bal) - 1;
            bal &= bal - 1;
            int j0 = (tb + tt) << 6;
            #pragma unroll
            for (int h = 0; h < 2; h++) {
                int j = j0 + h * 32 + lane;
                bool hit = false;
                int rj = 0;
                if (j < N_ANCH) {
                    rj = g_srank[j];
                    if (rj < ri) {   // potential suppressor (implies j valid)
                        float xx1 = fmaxf(x1, g_x1[j]);
                        float yy1 = fmaxf(y1, g_y1[j]);
                        float xx2 = fminf(x2, g_x2[j]);
                        float yy2 = fminf(y2, g_y2[j]);
                        float w  = fmaxf(__fadd_rn(__fsub_rn(xx2, xx1), 1.f), 0.f);
                        float hh = fmaxf(__fadd_rn(__fsub_rn(yy2, yy1), 1.f), 0.f);
                        float inter = __fmul_rn(w, hh);
                        float aj = g_area[j];
                        if (inter > 0.299f * fmaxf(ai, aj)) {
                            float iou = __fdiv_rn(inter, __fsub_rn(__fadd_rn(ai, aj), inter));
                            hit = iou > NMS_THF;
                        }
                    }
                }
                unsigned hb = __ballot_sync(FULLM, hit);
                if (hit) {
                    int off = cnt + __popc(hb & ((1u << lane) - 1));
                    if (off < CAP) g_nbr[(size_t)ri * CAP + off] = (unsigned short)rj;
                }
                cnt += __popc(hb);
            }
        }
    }
    if (lane == 0) g_ncnt[ri] = min(cnt, CAP);
}

// ---------------- rank-ordered fixed-point NMS resolve ----------------
// 2 bits per rank: bit0 = resolved, bit1 = kept
__global__ void __launch_bounds__(1024) k_resolve() {
    __shared__ unsigned long long state[NSTATE];
    __shared__ int more;
    int t = threadIdx.x;
    int kcnt = g_kcnt;
    for (int w = t; w < NSTATE; w += 1024) {
        int base = w << 5;
        unsigned long long sw = 0;
        for (int b = 0; b < 32; b++)
            if (base + b >= kcnt) sw |= 1ull << (2 * b);   // rank >= kcnt: resolved, not kept
        state[w] = sw;
    }
    if (t == 0) more = 0;
    __syncthreads();

    int chunk = (kcnt + 1023) >> 10;
    int lo = t * chunk, hi = min(lo + chunk, kcnt);
    for (;;) {
        int lm = 0;
        for (int r = lo; r < hi; r++) {
            unsigned long long sv = state[r >> 5] >> ((r & 31) * 2);
            if (sv & 1ull) continue;
            int cn = g_ncnt[r];
            const unsigned short* lst = g_nbr + (size_t)r * CAP;
            bool anyk = false, allres = true;
            for (int e = 0; e < cn; e++) {
                int c = lst[e];
                unsigned long long cs = state[c >> 5] >> ((c & 31) * 2);
                if (cs & 2ull) { anyk = true; break; }
                if (!(cs & 1ull)) allres = false;
            }
            if (anyk)
                atomicOr(&state[r >> 5], 1ull << ((r & 31) * 2));
            else if (allres)
                atomicOr(&state[r >> 5], 3ull << ((r & 31) * 2));
            else
                lm = 1;
        }
        if (lm) more = 1;
        __syncthreads();
        int m = more;
        __syncthreads();
        if (!m) break;
        if (t == 0) more = 0;
        __syncthreads();
    }
    for (int w = t; w < NSTATE; w += 1024) g_state[w] = state[w];
}

// ---------------- final masked write ----------------
__global__ void k_final(float* __restrict__ out) {
    int i = blockIdx.x * blockDim.x + threadIdx.x;
    if (i >= N_ANCH) return;
    float sc = g_sc[i];
    int ri = g_srank[i];
    unsigned long long sv = g_state[ri >> 5] >> ((ri & 31) * 2);
    bool kp = (sv & 2ull) != 0ull;   // kept implies score>0.5
    float f = kp ? 1.0f : 0.0f;
    out[i * 5 + 0] = __fmul_rn(g_x1[i], f);
    out[i * 5 + 1] = __fmul_rn(g_y1[i], f);
    out[i * 5 + 2] = __fmul_rn(g_x2[i], f);
    out[i * 5 + 3] = __fmul_rn(g_y2[i], f);
    out[i * 5 + 4] = __fmul_rn(sc, f);
}

extern "C" void kernel_launch(void* const* d_in, const int* in_sizes, int n_in,
                              void* d_out, int out_size) {
    (void)in_sizes; (void)n_in; (void)out_size;
    InPtrs p;
    for (int i = 0; i < 6; i++) {
        p.cls[i] = (const float*)d_in[2 * i];
        p.reg[i] = (const float*)d_in[2 * i + 1];
    }
    unsigned *kA, *kB; unsigned short *vA, *vB;
    cudaGetSymbolAddress((void**)&kA, g_keyA);
    cudaGetSymbolAddress((void**)&kB, g_keyB);
    cudaGetSymbolAddress((void**)&vA, g_valA);
    cudaGetSymbolAddress((void**)&vB, g_valB);

    k_decode<<<NBLK, 256>>>(p);

    k_hist<<<NBLK, 256>>>(kA, 0);
    k_scan1<<<512, 256>>>();
    k_scan2<<<1, 1024>>>();
    k_scatter<<<NBLK, 256>>>(kA, vA, kB, vB, 0);
    k_hist<<<NBLK, 256>>>(kB, 12);
    k_scan1<<<512, 256>>>();
    k_scan2<<<1, 1024>>>();
    k_scatter<<<NBLK, 256>>>(kB, vB, kA, vA, 12);

    k_srank<<<NBLK, 256>>>();
    k_nbr<<<(N_ANCH * 32 + 255) / 256, 256>>>();
    k_resolve<<<1, 1024>>>();
    k_final<<<NBLK, 256>>>((float*)d_out);
}

// round 6
// speedup vs baseline: 9.2321x; 1.1991x over previous
#include <cuda_runtime.h>
#include <math.h>

#define N_ANCH 21840
#define NWORDS 342            // ceil(21840/64) tiles
#define NSTATE 683            // ceil(21840/32), 2 bits per rank
#define NBLK   86             // ceil(21840/256)
#define NDIG   4096           // 12-bit high digit
#define CAP    192            // max higher-rank suppressors per box
#define NMS_THF 0.3f
#define FIN_THF 0.5f
#define FULLM 0xFFFFFFFFu

// ---- static device scratch (zero-initialized at module load) ----
__device__ float g_x1[N_ANCH], g_y1[N_ANCH], g_x2[N_ANCH], g_y2[N_ANCH];
__device__ float g_sc[N_ANCH], g_area[N_ANCH];
__device__ unsigned g_key[N_ANCH];
__device__ int g_hist[NDIG];            // re-zeroed by k_final each replay
__device__ int g_base[NDIG], g_cursor[NDIG];
__device__ unsigned g_bin[N_ANCH];      // (low12 << 15) | idx
__device__ int g_srank[N_ANCH];
__device__ int g_kcnt;
__device__ float g_tminx1[NWORDS], g_tminy1[NWORDS], g_tmaxx2[NWORDS], g_tmaxy2[NWORDS];
__device__ float g_tamin[NWORDS], g_tamax[NWORDS];
__device__ unsigned short g_nbr[(size_t)N_ANCH * CAP];  // by rank
__device__ int g_ncnt[N_ANCH];                           // by rank
__device__ unsigned long long g_state[NSTATE];

struct InPtrs { const float* cls[6]; const float* reg[6]; };

// ---------------- K1: decode (bit-exact) + key + hist + tile bboxes ----------------
__global__ void k_decode(InPtrs in) {
    __shared__ float m0[256], m1[256], m2[256], m3[256], m4[256], m5[256];
    int t = threadIdx.x;
    int i = blockIdx.x * 256 + t;
    bool on = i < N_ANCH;

    float x1 = 0.f, y1 = 0.f, x2 = 0.f, y2 = 0.f, prob = 0.f, area = 0.f;
    if (on) {
        const int offs[7]   = {0, 16384, 20480, 21504, 21760, 21824, 21840};
        const int maps[6]   = {128, 64, 32, 16, 8, 4};
        const float strd[6] = {4.f, 8.f, 16.f, 32.f, 64.f, 128.f};
        int sc = 0;
        #pragma unroll
        for (int k = 0; k < 5; k++) if (i >= offs[k + 1]) sc = k + 1;
        int local = i - offs[sc];
        int W = maps[sc];
        int y = local / W, x = local - y * W;
        int HW = W * W;
        const float* cls = in.cls[sc];
        const float* reg = in.reg[sc];

        float c0 = cls[local], c1 = cls[HW + local];
        float m  = fmaxf(c0, c1);
        float e0 = expf(__fsub_rn(c0, m));
        float e1 = expf(__fsub_rn(c1, m));
        prob = __fdiv_rn(e1, __fadd_rn(e0, e1));

        float s   = strd[sc];
        float pwh = s * 4.0f;
        float pcx = __fadd_rn(0.5f * s, __fmul_rn((float)x, s));
        float pcy = __fadd_rn(0.5f * s, __fmul_rn((float)y, s));
        float l0 = reg[local], l1 = reg[HW + local];
        float l2 = reg[2 * HW + local], l3 = reg[3 * HW + local];
        float cx = __fadd_rn(pcx, __fmul_rn(__fmul_rn(l0, 0.1f), pwh));
        float cy = __fadd_rn(pcy, __fmul_rn(__fmul_rn(l1, 0.1f), pwh));
        float w  = __fmul_rn(pwh, expf(__fmul_rn(l2, 0.2f)));
        float h  = __fmul_rn(pwh, expf(__fmul_rn(l3, 0.2f)));
        x1 = __fsub_rn(cx, __fmul_rn(w, 0.5f));
        y1 = __fsub_rn(cy, __fmul_rn(h, 0.5f));
        x2 = __fadd_rn(x1, w);
        y2 = __fadd_rn(y1, h);
        area = __fmul_rn(__fadd_rn(__fsub_rn(x2, x1), 1.0f),
                         __fadd_rn(__fsub_rn(y2, y1), 1.0f));

        g_x1[i] = x1; g_y1[i] = y1; g_x2[i] = x2; g_y2[i] = y2;
        g_sc[i] = prob; g_area[i] = area;

        // 24-bit key: prob in (0.5,1] -> [0, 0x7FFFFF]; ascending == descending score
        unsigned u   = __float_as_uint(prob);
        unsigned k24 = (~(u | 0x80000000u)) - 0x407FFFFFu;
        bool valid = prob > FIN_THF;
        g_key[i] = valid ? k24 : 0xFFFFFFFFu;
        if (valid) atomicAdd(&g_hist[k24 >> 12], 1);
    }

    // fused per-64 tile bboxes (valid boxes only)
    bool v = on && (prob > FIN_THF);
    m0[t] = v ? x1 :  1e30f;
    m1[t] = v ? y1 :  1e30f;
    m2[t] = v ? x2 : -1e30f;
    m3[t] = v ? y2 : -1e30f;
    m4[t] = v ? area :  1e30f;
    m5[t] = v ? area : -1e30f;
    int o = t & 63;
    for (int s = 32; s > 0; s >>= 1) {
        __syncthreads();
        if (o < s) {
            m0[t] = fminf(m0[t], m0[t + s]);
            m1[t] = fminf(m1[t], m1[t + s]);
            m2[t] = fmaxf(m2[t], m2[t + s]);
            m3[t] = fmaxf(m3[t], m3[t + s]);
            m4[t] = fminf(m4[t], m4[t + s]);
            m5[t] = fmaxf(m5[t], m5[t + s]);
        }
    }
    if (o == 0) {
        int tile = blockIdx.x * 4 + (t >> 6);
        if (tile < NWORDS) {
            g_tminx1[tile] = m0[t]; g_tminy1[tile] = m1[t];
            g_tmaxx2[tile] = m2[t]; g_tmaxy2[tile] = m3[t];
            g_tamin[tile]  = m4[t]; g_tamax[tile]  = m5[t];
        }
    }
}

// ---------------- K2: exclusive scan of 4096 digit counts ----------------
__global__ void __launch_bounds__(1024) k_scan() {
    __shared__ int wsum[32];
    int t = threadIdx.x, lane = t & 31, wid = t >> 5;
    int a0 = g_hist[4 * t], a1 = g_hist[4 * t + 1], a2 = g_hist[4 * t + 2], a3 = g_hist[4 * t + 3];
    int s = a0 + a1 + a2 + a3;
    int x = s;
    #pragma unroll
    for (int k = 1; k < 32; k <<= 1) { int y = __shfl_up_sync(FULLM, x, k); if (lane >= k) x += y; }
    if (lane == 31) wsum[wid] = x;
    __syncthreads();
    if (wid == 0) {
        int wv = wsum[lane];
        #pragma unroll
        for (int k = 1; k < 32; k <<= 1) { int y = __shfl_up_sync(FULLM, wv, k); if (lane >= k) wv += y; }
        wsum[lane] = wv;
    }
    __syncthreads();
    int base = x - s + ((wid > 0) ? wsum[wid - 1] : 0);
    int b0 = base, b1 = base + a0, b2 = b1 + a1, b3 = b2 + a2;
    g_base[4 * t] = b0;     g_cursor[4 * t] = b0;
    g_base[4 * t + 1] = b1; g_cursor[4 * t + 1] = b1;
    g_base[4 * t + 2] = b2; g_cursor[4 * t + 2] = b2;
    g_base[4 * t + 3] = b3; g_cursor[4 * t + 3] = b3;
    if (t == 1023) g_kcnt = b3 + a3;   // total valid (digits 0x800..0xFFF are invalid/empty)
}

// ---------------- K3: unstable scatter into bins ----------------
__global__ void k_scatter() {
    int i = blockIdx.x * 256 + threadIdx.x;
    if (i >= N_ANCH) return;
    unsigned k = g_key[i];
    if (k == 0xFFFFFFFFu) return;
    int d = k >> 12;
    int pos = atomicAdd(&g_cursor[d], 1);
    g_bin[pos] = ((k & 0xFFFu) << 15) | (unsigned)i;   // (low12, idx): unique, stable order
}

// ---------------- K4: in-bin ranking (warp per bin) ----------------
__global__ void k_binsort() {
    int wid = threadIdx.x >> 5, lane = threadIdx.x & 31;
    int d = blockIdx.x * 8 + wid;
    if (d >= NDIG - 1) return;   // skip invalid bin 4095 (and OOB)
    int base = g_base[d];
    int n = g_cursor[d] - base;
    if (n == 0) return;
    if (n <= 32) {
        unsigned rec = (lane < n) ? g_bin[base + lane] : 0xFFFFFFFFu;
        int r = 0;
        for (int k = 0; k < n; k++) {
            unsigned other = __shfl_sync(FULLM, rec, k);
            r += (other < rec) ? 1 : 0;
        }
        if (lane < n) g_srank[rec & 0x7FFFu] = base + r;
    } else {
        for (int e = lane; e < n; e += 32) {
            unsigned rec = g_bin[base + e];
            int r = 0;
            for (int k = 0; k < n; k++) r += (g_bin[base + k] < rec) ? 1 : 0;
            g_srank[rec & 0x7FFFu] = base + r;
        }
    }
}

// ---------------- K5: sparse suppressor lists (warp per box, rank-indexed) ----------------
__global__ void k_nbr() {
    int i = (blockIdx.x * blockDim.x + threadIdx.x) >> 5;
    int lane = threadIdx.x & 31;
    if (i >= N_ANCH) return;
    if (!(g_sc[i] > FIN_THF)) return;
    float x1 = g_x1[i], y1 = g_y1[i], x2 = g_x2[i], y2 = g_y2[i], ai = g_area[i];
    int ri = g_srank[i];
    int cnt = 0;
    for (int tb = 0; tb < NWORDS; tb += 32) {
        int t = tb + lane;
        bool act = false;
        if (t < NWORDS) {
            float bw = __fadd_rn(__fsub_rn(fminf(x2, g_tmaxx2[t]), fmaxf(x1, g_tminx1[t])), 1.0f);
            float bh = __fadd_rn(__fsub_rn(fminf(y2, g_tmaxy2[t]), fmaxf(y1, g_tminy1[t])), 1.0f);
            float lo = fminf(ai, g_tamax[t]);
            float hi = fmaxf(ai, g_tamin[t]);
            act = (bw > 0.f) && (bh > 0.f) && (lo > 0.299f * hi);  // conservative
        }
        unsigned bal = __ballot_sync(FULLM, act);
        while (bal) {
            int tt = __ffs(bal) - 1;
            bal &= bal - 1;
            int j0 = (tb + tt) << 6;
            #pragma unroll
            for (int h = 0; h < 2; h++) {
                int j = j0 + h * 32 + lane;
                bool hit = false;
                int rj = 0;
                if (j < N_ANCH) {
                    rj = g_srank[j];
                    if ((g_sc[j] > FIN_THF) && rj < ri) {   // potential suppressor
                        float xx1 = fmaxf(x1, g_x1[j]);
                        float yy1 = fmaxf(y1, g_y1[j]);
                        float xx2 = fminf(x2, g_x2[j]);
                        float yy2 = fminf(y2, g_y2[j]);
                        float w  = fmaxf(__fadd_rn(__fsub_rn(xx2, xx1), 1.f), 0.f);
                        float hh = fmaxf(__fadd_rn(__fsub_rn(yy2, yy1), 1.f), 0.f);
                        float inter = __fmul_rn(w, hh);
                        float aj = g_area[j];
                        if (inter > 0.299f * fmaxf(ai, aj)) {
                            float iou = __fdiv_rn(inter, __fsub_rn(__fadd_rn(ai, aj), inter));
                            hit = iou > NMS_THF;
                        }
                    }
                }
                unsigned hb = __ballot_sync(FULLM, hit);
                if (hit) {
                    int off = cnt + __popc(hb & ((1u << lane) - 1));
                    if (off < CAP) g_nbr[(size_t)ri * CAP + off] = (unsigned short)rj;
                }
                cnt += __popc(hb);
            }
        }
    }
    if (lane == 0) g_ncnt[ri] = min(cnt, CAP);
}

// ---------------- K6: rank-ordered fixed-point NMS resolve ----------------
// 2 bits per rank: bit0 = resolved, bit1 = kept
__global__ void __launch_bounds__(1024) k_resolve() {
    __shared__ unsigned long long state[NSTATE];
    __shared__ int more;
    int t = threadIdx.x;
    int kcnt = g_kcnt;
    for (int w = t; w < NSTATE; w += 1024) {
        int base = w << 5;
        unsigned long long sw = 0;
        for (int b = 0; b < 32; b++)
            if (base + b >= kcnt) sw |= 1ull << (2 * b);   // rank >= kcnt: resolved, not kept
        state[w] = sw;
    }
    if (t == 0) more = 0;
    __syncthreads();

    int chunk = (kcnt + 1023) >> 10;
    int lo = t * chunk, hi = min(lo + chunk, kcnt);
    bool mydone = (lo >= hi);
    for (;;) {
        int lm = 0;
        if (!mydone) {
            bool alldone = true;
            for (int r = lo; r < hi; r++) {
                unsigned long long sv = state[r >> 5] >> ((r & 31) * 2);
                if (sv & 1ull) continue;
                int cn = g_ncnt[r];
                const unsigned short* lst = g_nbr + (size_t)r * CAP;
                bool anyk = false, allres = true;
                for (int e = 0; e < cn; e++) {
                    int c = lst[e];
                    unsigned long long cs = state[c >> 5] >> ((c & 31) * 2);
                    if (cs & 2ull) { anyk = true; break; }
                    if (!(cs & 1ull)) allres = false;
                }
                if (anyk)
                    atomicOr(&state[r >> 5], 1ull << ((r & 31) * 2));
                else if (allres)
                    atomicOr(&state[r >> 5], 3ull << ((r & 31) * 2));
                else { lm = 1; alldone = false; }
            }
            mydone = alldone;
        }
        if (lm) more = 1;
        __syncthreads();
        int m = more;
        __syncthreads();
        if (!m) break;
        if (t == 0) more = 0;
        __syncthreads();
    }
    for (int w = t; w < NSTATE; w += 1024) g_state[w] = state[w];
}

// ---------------- K7: final masked write + hist re-zero for next replay ----------------
__global__ void k_final(float* __restrict__ out) {
    int i = blockIdx.x * blockDim.x + threadIdx.x;
    if (i < NDIG) g_hist[i] = 0;
    if (i >= N_ANCH) return;
    float sc = g_sc[i];
    bool valid = sc > FIN_THF;
    int ri = valid ? g_srank[i] : 0;
    unsigned long long sv = g_state[ri >> 5] >> ((ri & 31) * 2);
    bool kp = valid && ((sv & 2ull) != 0ull);
    float f = kp ? 1.0f : 0.0f;
    out[i * 5 + 0] = __fmul_rn(g_x1[i], f);
    out[i * 5 + 1] = __fmul_rn(g_y1[i], f);
    out[i * 5 + 2] = __fmul_rn(g_x2[i], f);
    out[i * 5 + 3] = __fmul_rn(g_y2[i], f);
    out[i * 5 + 4] = __fmul_rn(sc, f);
}

extern "C" void kernel_launch(void* const* d_in, const int* in_sizes, int n_in,
                              void* d_out, int out_size) {
    (void)in_sizes; (void)n_in; (void)out_size;
    InPtrs p;
    for (int i = 0; i < 6; i++) {
        p.cls[i] = (const float*)d_in[2 * i];
        p.reg[i] = (const float*)d_in[2 * i + 1];
    }
    k_decode<<<NBLK, 256>>>(p);
    k_scan<<<1, 1024>>>();
    k_scatter<<<NBLK, 256>>>();
    k_binsort<<<512, 256>>>();
    k_nbr<<<(N_ANCH * 32 + 255) / 256, 256>>>();
    k_resolve<<<1, 1024>>>();
    k_final<<<NBLK, 256>>>((float*)d_out);
}